// round 1
// baseline (speedup 1.0000x reference)
#include <cuda_runtime.h>
#include <math.h>

// Problem constants
#define S_DIM 512
#define N_DIM 384
#define CM 64
#define CZ 128
#define H_DIM 8
#define C_DIM 32
#define HC 256           // H*C
#define SN (S_DIM * N_DIM)      // 196608 rows of m
#define M_DIM (S_DIM * C_DIM)   // 16384 = columns of the einsum GEMM

// ---------------- scratch (device globals; no allocation allowed) ----------------
__device__ float g_mn[SN * CM];                    // normalized m          (48 MB)
__device__ float g_v[H_DIM * N_DIM * M_DIM];       // v  [h][j][s*32+c]     (192 MB)
__device__ float g_gate[SN * HC];                  // sigmoid gate [row][k] (192 MB)
__device__ float g_b[H_DIM * N_DIM * N_DIM];       // bias  [h][j][i]       (4.5 MB)
__device__ float g_w[H_DIM * N_DIM * N_DIM];       // softmax w [h][i][j]   (4.5 MB)
__device__ float g_wv[H_DIM * N_DIM * M_DIM];      // wv [h][i][s*32+c]     (192 MB)

// ---------------- K1a: LayerNorm over c_m=64, one warp per row ----------------
__global__ void ln_m_kernel(const float* __restrict__ x,
                            const float* __restrict__ gamma,
                            const float* __restrict__ beta) {
    int warp = (blockIdx.x * blockDim.x + threadIdx.x) >> 5;
    int lane = threadIdx.x & 31;
    if (warp >= SN) return;
    const float* row = x + (size_t)warp * CM;
    float a = row[lane];
    float b = row[lane + 32];
    float s = a + b;
    float ss = a * a + b * b;
    #pragma unroll
    for (int o = 16; o > 0; o >>= 1) {
        s  += __shfl_xor_sync(0xffffffffu, s,  o);
        ss += __shfl_xor_sync(0xffffffffu, ss, o);
    }
    float mu  = s * (1.0f / 64.0f);
    float var = ss * (1.0f / 64.0f) - mu * mu;
    float inv = rsqrtf(var + 1e-5f);
    float* out = g_mn + (size_t)warp * CM;
    out[lane]      = (a - mu) * inv * gamma[lane]      + beta[lane];
    out[lane + 32] = (b - mu) * inv * gamma[lane + 32] + beta[lane + 32];
}

// ---------------- K1b: [SN x 64] @ [64 x 512] -> v (layout swap) + sigmoid gate ----
// 128x128 tile, TK=8, 256 threads, 8x8 microtile.
__global__ __launch_bounds__(256) void gemm_mw_kernel(const float* __restrict__ W1,
                                                      const float* __restrict__ W3) {
    __shared__ __align__(16) float Ast[8][132];   // [k][i], pad 132 (conflict-free, 16B rows)
    __shared__ __align__(16) float Bs[8][128];    // [k][col]
    int t  = threadIdx.x;
    int tx = t & 15;
    int ty = t >> 4;
    int i0 = blockIdx.x * 128;
    int cy = blockIdx.y;                          // 0,1 -> W1 ; 2,3 -> W3
    const float* B = (cy < 2) ? W1 : W3;
    int col0 = (cy & 1) * 128;

    float acc[8][8];
    #pragma unroll
    for (int a = 0; a < 8; a++)
        #pragma unroll
        for (int b = 0; b < 8; b++) acc[a][b] = 0.0f;

    for (int k0 = 0; k0 < CM; k0 += 8) {
        #pragma unroll
        for (int l = 0; l < 4; l++) {
            int idx = t + l * 256;
            int kk = idx & 7, ii = idx >> 3;
            Ast[kk][ii] = g_mn[(size_t)(i0 + ii) * CM + k0 + kk];
        }
        #pragma unroll
        for (int l = 0; l < 4; l++) {
            int idx = t + l * 256;
            int mm = idx & 127, kk = idx >> 7;
            Bs[kk][mm] = B[(k0 + kk) * HC + col0 + mm];
        }
        __syncthreads();
        #pragma unroll
        for (int kk = 0; kk < 8; kk++) {
            float ra[8], rb[8];
            *(float4*)(ra)     = *(const float4*)&Ast[kk][ty * 8];
            *(float4*)(ra + 4) = *(const float4*)&Ast[kk][ty * 8 + 4];
            *(float4*)(rb)     = *(const float4*)&Bs[kk][tx * 8];
            *(float4*)(rb + 4) = *(const float4*)&Bs[kk][tx * 8 + 4];
            #pragma unroll
            for (int a = 0; a < 8; a++)
                #pragma unroll
                for (int b = 0; b < 8; b++) acc[a][b] += ra[a] * rb[b];
        }
        __syncthreads();
    }

    int colg = cy * 128 + tx * 8;                 // global column 0..511
    #pragma unroll
    for (int a = 0; a < 8; a++) {
        int i = i0 + ty * 8 + a;                  // row = s*N + n
        int s = i / N_DIM;
        int n = i % N_DIM;
        if (cy < 2) {
            int h = colg >> 5;
            int c = colg & 31;                    // multiple of 8; stays in one h
            float* dst = g_v + (size_t)(h * N_DIM + n) * M_DIM + s * C_DIM + c;
            *(float4*)(dst)     = *(float4*)&acc[a][0];
            *(float4*)(dst + 4) = *(float4*)&acc[a][4];
        } else {
            float* dst = g_gate + (size_t)i * HC + (colg - HC);
            float o[8];
            #pragma unroll
            for (int b = 0; b < 8; b++) o[b] = 1.0f / (1.0f + __expf(-acc[a][b]));
            *(float4*)(dst)     = *(float4*)&o[0];
            *(float4*)(dst + 4) = *(float4*)&o[4];
        }
    }
}

// ---------------- K2: LN(z) over 128 + @W2 -> b[h][j][i] ----------------
__global__ void ln_z_bias_kernel(const float* __restrict__ z,
                                 const float* __restrict__ gz,
                                 const float* __restrict__ bz,
                                 const float* __restrict__ W2) {
    __shared__ float szn[CZ];
    __shared__ float sW2[CZ * H_DIM];
    __shared__ float red[8];
    int t = threadIdx.x;                          // 128
    int j = blockIdx.x;
    int i = blockIdx.y;
    const float* row = z + ((size_t)i * N_DIM + j) * CZ;
    float x = row[t];
    #pragma unroll
    for (int l = 0; l < 8; l++) sW2[t + l * 128] = W2[t + l * 128];

    float s = x, ss = x * x;
    #pragma unroll
    for (int o = 16; o > 0; o >>= 1) {
        s  += __shfl_xor_sync(0xffffffffu, s,  o);
        ss += __shfl_xor_sync(0xffffffffu, ss, o);
    }
    int warp = t >> 5, lane = t & 31;
    if (lane == 0) { red[warp] = s; red[4 + warp] = ss; }
    __syncthreads();
    float stot  = red[0] + red[1] + red[2] + red[3];
    float sstot = red[4] + red[5] + red[6] + red[7];
    float mu  = stot * (1.0f / 128.0f);
    float var = sstot * (1.0f / 128.0f) - mu * mu;
    float inv = rsqrtf(var + 1e-5f);
    szn[t] = (x - mu) * inv * gz[t] + bz[t];
    __syncthreads();
    if (t < H_DIM) {
        float acc = 0.0f;
        #pragma unroll 8
        for (int k = 0; k < CZ; k++) acc += szn[k] * sW2[k * H_DIM + t];
        g_b[((size_t)t * N_DIM + j) * N_DIM + i] = acc;
    }
}

// ---------------- K3: softmax over i (contiguous), write w[h][i][j] ----------------
__global__ void softmax_kernel() {
    __shared__ float redm[4];
    __shared__ float reds[4];
    int j = blockIdx.x;
    int h = blockIdx.y;
    int t = threadIdx.x;                          // 128
    const float* col = g_b + ((size_t)h * N_DIM + j) * N_DIM;
    float v0 = col[t], v1 = col[t + 128], v2 = col[t + 256];
    float mx = fmaxf(v0, fmaxf(v1, v2));
    #pragma unroll
    for (int o = 16; o > 0; o >>= 1) mx = fmaxf(mx, __shfl_xor_sync(0xffffffffu, mx, o));
    int warp = t >> 5, lane = t & 31;
    if (lane == 0) redm[warp] = mx;
    __syncthreads();
    mx = fmaxf(fmaxf(redm[0], redm[1]), fmaxf(redm[2], redm[3]));
    float e0 = __expf(v0 - mx), e1 = __expf(v1 - mx), e2 = __expf(v2 - mx);
    float sm = e0 + e1 + e2;
    #pragma unroll
    for (int o = 16; o > 0; o >>= 1) sm += __shfl_xor_sync(0xffffffffu, sm, o);
    if (lane == 0) reds[warp] = sm;
    __syncthreads();
    float inv = 1.0f / (reds[0] + reds[1] + reds[2] + reds[3]);
    float* wbase = g_w + (size_t)h * N_DIM * N_DIM + j;
    wbase[(size_t)(t)       * N_DIM] = e0 * inv;
    wbase[(size_t)(t + 128) * N_DIM] = e1 * inv;
    wbase[(size_t)(t + 256) * N_DIM] = e2 * inv;
}

// ---------------- K4: per-head GEMM  wv_h[i,m] = w_h[i,j] @ v_h[j,m] ----------------
// I=384 (3 tiles), M=16384 (128 tiles), K=384. Same 128x128x8 structure.
__global__ __launch_bounds__(256) void gemm_wv_kernel() {
    __shared__ __align__(16) float Ast[8][132];
    __shared__ __align__(16) float Bs[8][128];
    int t  = threadIdx.x;
    int tx = t & 15;
    int ty = t >> 4;
    int m0 = blockIdx.x * 128;
    int i0 = blockIdx.y * 128;
    int h  = blockIdx.z;
    const float* A  = g_w + (size_t)h * N_DIM * N_DIM;   // [i][j]
    const float* Bv = g_v + (size_t)h * N_DIM * M_DIM;   // [j][m]

    float acc[8][8];
    #pragma unroll
    for (int a = 0; a < 8; a++)
        #pragma unroll
        for (int b = 0; b < 8; b++) acc[a][b] = 0.0f;

    for (int k0 = 0; k0 < N_DIM; k0 += 8) {
        #pragma unroll
        for (int l = 0; l < 4; l++) {
            int idx = t + l * 256;
            int kk = idx & 7, ii = idx >> 3;
            Ast[kk][ii] = A[(size_t)(i0 + ii) * N_DIM + k0 + kk];
        }
        #pragma unroll
        for (int l = 0; l < 4; l++) {
            int idx = t + l * 256;
            int mm = idx & 127, kk = idx >> 7;
            Bs[kk][mm] = Bv[(size_t)(k0 + kk) * M_DIM + m0 + mm];
        }
        __syncthreads();
        #pragma unroll
        for (int kk = 0; kk < 8; kk++) {
            float ra[8], rb[8];
            *(float4*)(ra)     = *(const float4*)&Ast[kk][ty * 8];
            *(float4*)(ra + 4) = *(const float4*)&Ast[kk][ty * 8 + 4];
            *(float4*)(rb)     = *(const float4*)&Bs[kk][tx * 8];
            *(float4*)(rb + 4) = *(const float4*)&Bs[kk][tx * 8 + 4];
            #pragma unroll
            for (int a = 0; a < 8; a++)
                #pragma unroll
                for (int b = 0; b < 8; b++) acc[a][b] += ra[a] * rb[b];
        }
        __syncthreads();
    }

    float* dst0 = g_wv + (size_t)h * N_DIM * M_DIM + m0 + tx * 8;
    #pragma unroll
    for (int a = 0; a < 8; a++) {
        float* dst = dst0 + (size_t)(i0 + ty * 8 + a) * M_DIM;
        *(float4*)(dst)     = *(float4*)&acc[a][0];
        *(float4*)(dst + 4) = *(float4*)&acc[a][4];
    }
}

// ---------------- K5: out[r,:] = (gate[r,:] * wv_gather[r,:]) @ W4 ----------------
// 32 rows/block, 256 threads: 8 threads per row, 8 outputs each. W4 via L1 (__ldg).
#define K5_PITCH 264
__global__ __launch_bounds__(256) void final_kernel(const float* __restrict__ W4,
                                                    float* __restrict__ out) {
    __shared__ __align__(16) float so[32 * K5_PITCH];
    int t = threadIdx.x;
    int r0 = blockIdx.x * 32;

    // stage o = gate * wv for 32 rows
    #pragma unroll 4
    for (int l = 0; l < 32; l++) {
        int idx = t + l * 256;
        int rr = idx >> 8;
        int k  = idx & 255;
        int r  = r0 + rr;
        int s  = r / N_DIM;
        int n  = r % N_DIM;
        int h  = k >> 5;
        int c  = k & 31;
        float wv = g_wv[(size_t)(h * N_DIM + n) * M_DIM + s * C_DIM + c];
        float gt = g_gate[(size_t)r * HC + k];
        so[rr * K5_PITCH + k] = wv * gt;
    }
    __syncthreads();

    int rowg = t >> 3;
    int g8   = (t & 7) * 8;
    const float* orow = so + rowg * K5_PITCH;
    float acc[8];
    #pragma unroll
    for (int b = 0; b < 8; b++) acc[b] = 0.0f;

    for (int k = 0; k < HC; k += 4) {
        float4 o4 = *(const float4*)(orow + k);
        float ov[4] = {o4.x, o4.y, o4.z, o4.w};
        #pragma unroll
        for (int u = 0; u < 4; u++) {
            float4 w0 = __ldg((const float4*)(W4 + (size_t)(k + u) * CM + g8));
            float4 w1 = __ldg((const float4*)(W4 + (size_t)(k + u) * CM + g8 + 4));
            acc[0] += ov[u] * w0.x; acc[1] += ov[u] * w0.y;
            acc[2] += ov[u] * w0.z; acc[3] += ov[u] * w0.w;
            acc[4] += ov[u] * w1.x; acc[5] += ov[u] * w1.y;
            acc[6] += ov[u] * w1.z; acc[7] += ov[u] * w1.w;
        }
    }
    float* dst = out + (size_t)(r0 + rowg) * CM + g8;
    *(float4*)(dst)     = *(float4*)&acc[0];
    *(float4*)(dst + 4) = *(float4*)&acc[4];
}

// ---------------- launch ----------------
extern "C" void kernel_launch(void* const* d_in, const int* in_sizes, int n_in,
                              void* d_out, int out_size) {
    const float* m_si    = (const float*)d_in[0];
    const float* z_ij    = (const float*)d_in[1];
    const float* gamma_m = (const float*)d_in[2];
    const float* beta_m  = (const float*)d_in[3];
    const float* W1      = (const float*)d_in[4];
    const float* gamma_z = (const float*)d_in[5];
    const float* beta_z  = (const float*)d_in[6];
    const float* W2      = (const float*)d_in[7];
    const float* W3      = (const float*)d_in[8];
    const float* W4      = (const float*)d_in[9];
    float* out = (float*)d_out;

    // K1a: layernorm of m (warp per row, 8 rows per block)
    ln_m_kernel<<<SN / 8, 256>>>(m_si, gamma_m, beta_m);

    // K1b: m @ [W1 | W3]  -> v (relayout) + sigmoid gate
    gemm_mw_kernel<<<dim3(SN / 128, 4), 256>>>(W1, W3);

    // K2: layernorm(z) @ W2 -> b[h][j][i]
    ln_z_bias_kernel<<<dim3(N_DIM, N_DIM), 128>>>(z_ij, gamma_z, beta_z, W2);

    // K3: softmax over i -> w[h][i][j]
    softmax_kernel<<<dim3(N_DIM, H_DIM), 128>>>();

    // K4: 8 head GEMMs, wv_h = w_h @ v_h
    gemm_wv_kernel<<<dim3(M_DIM / 128, N_DIM / 128, H_DIM), 256>>>();

    // K5: gate * wv, reshape, @ W4
    final_kernel<<<SN / 32, 256>>>(W4, out);
}

// round 2
// speedup vs baseline: 2.5629x; 2.5629x over previous
#include <cuda_runtime.h>
#include <math.h>
#include <stdint.h>

// Problem constants
#define S_DIM 512
#define N_DIM 384
#define CM 64
#define CZ 128
#define H_DIM 8
#define C_DIM 32
#define HC 256                  // H*C
#define SN (S_DIM * N_DIM)      // 196608 rows of m
#define M_DIM (S_DIM * C_DIM)   // 16384 = columns of the einsum GEMM

// ---------------- scratch (device globals; no allocation allowed) ----------------
__device__ float g_mn[SN * CM];                    // normalized m          (48 MB)
__device__ float g_v[H_DIM * N_DIM * M_DIM];       // v  [h][j][s*32+c]     (192 MB)
__device__ float g_gate[SN * HC];                  // sigmoid gate [row][k] (192 MB)
__device__ float g_b[H_DIM * N_DIM * N_DIM];       // bias  [h][j][i]       (4.5 MB)
__device__ float g_w[H_DIM * N_DIM * N_DIM];       // softmax w [h][i][j]   (4.5 MB)
__device__ float g_wv[H_DIM * N_DIM * M_DIM];      // wv [h][i][s*32+c]     (192 MB)

// ---------------- mma helpers ----------------
__device__ __forceinline__ uint32_t f2tf(float x) {
    uint32_t y;
    asm("cvt.rna.tf32.f32 %0, %1;" : "=r"(y) : "f"(x));
    return y;
}
__device__ __forceinline__ void mma8(float c[4], const uint32_t a[4], const uint32_t b[2]) {
    asm volatile(
        "mma.sync.aligned.m16n8k8.row.col.f32.tf32.tf32.f32 "
        "{%0,%1,%2,%3}, {%4,%5,%6,%7}, {%8,%9}, {%0,%1,%2,%3};\n"
        : "+f"(c[0]), "+f"(c[1]), "+f"(c[2]), "+f"(c[3])
        : "r"(a[0]), "r"(a[1]), "r"(a[2]), "r"(a[3]), "r"(b[0]), "r"(b[1]));
}

// ---------------- K1a: LayerNorm over c_m=64, one warp per row ----------------
__global__ void ln_m_kernel(const float* __restrict__ x,
                            const float* __restrict__ gamma,
                            const float* __restrict__ beta) {
    int warp = (blockIdx.x * blockDim.x + threadIdx.x) >> 5;
    int lane = threadIdx.x & 31;
    if (warp >= SN) return;
    const float* row = x + (size_t)warp * CM;
    float a = row[lane];
    float b = row[lane + 32];
    float s = a + b;
    float ss = a * a + b * b;
    #pragma unroll
    for (int o = 16; o > 0; o >>= 1) {
        s  += __shfl_xor_sync(0xffffffffu, s,  o);
        ss += __shfl_xor_sync(0xffffffffu, ss, o);
    }
    float mu  = s * (1.0f / 64.0f);
    float var = ss * (1.0f / 64.0f) - mu * mu;
    float inv = rsqrtf(var + 1e-5f);
    float* out = g_mn + (size_t)warp * CM;
    out[lane]      = (a - mu) * inv * gamma[lane]      + beta[lane];
    out[lane + 32] = (b - mu) * inv * gamma[lane + 32] + beta[lane + 32];
}

// ---------------- K1b: tf32-MMA GEMM  [SN x 64] @ [64 x 512] -> v relayout + gate ----
// Block 128 rows x 128 cols, K=64 chunked by 16. 8 warps: 2 (M) x 4 (N), warp tile 64x32.
__global__ __launch_bounds__(256) void gemm_mw_mma(const float* __restrict__ W1,
                                                   const float* __restrict__ W3) {
    __shared__ uint32_t As[128][20];   // [i][k], pitch 20 -> conflict-free frag loads
    __shared__ uint32_t Bs[16][136];   // [k][col], pitch 136
    int t = threadIdx.x;
    int lane = t & 31, w = t >> 5;
    int wm = w & 1, wn = w >> 1;
    int g = lane >> 2, tig = lane & 3;
    int i0 = blockIdx.x * 128;
    int cy = blockIdx.y;                          // 0,1 -> W1 ; 2,3 -> W3
    const float* B = (cy < 2) ? W1 : W3;
    int col0 = (cy & 1) * 128;

    float acc[4][4][4];
    #pragma unroll
    for (int a = 0; a < 4; a++)
        #pragma unroll
        for (int b = 0; b < 4; b++)
            #pragma unroll
            for (int q = 0; q < 4; q++) acc[a][b][q] = 0.0f;

    for (int k0 = 0; k0 < CM; k0 += 16) {
        // stage A: 128 x 16
        {
            int row = t >> 1, kh = (t & 1) * 8;
            const float* src = g_mn + (size_t)(i0 + row) * CM + k0 + kh;
            float4 v0 = *(const float4*)src;
            float4 v1 = *(const float4*)(src + 4);
            uint32_t* d = &As[row][kh];
            d[0] = f2tf(v0.x); d[1] = f2tf(v0.y); d[2] = f2tf(v0.z); d[3] = f2tf(v0.w);
            d[4] = f2tf(v1.x); d[5] = f2tf(v1.y); d[6] = f2tf(v1.z); d[7] = f2tf(v1.w);
        }
        // stage B: 16 x 128
        {
            int kk = t >> 4, mc = (t & 15) * 8;
            const float* src = B + (size_t)(k0 + kk) * HC + col0 + mc;
            float4 v0 = *(const float4*)src;
            float4 v1 = *(const float4*)(src + 4);
            uint32_t* d = &Bs[kk][mc];
            d[0] = f2tf(v0.x); d[1] = f2tf(v0.y); d[2] = f2tf(v0.z); d[3] = f2tf(v0.w);
            d[4] = f2tf(v1.x); d[5] = f2tf(v1.y); d[6] = f2tf(v1.z); d[7] = f2tf(v1.w);
        }
        __syncthreads();
        #pragma unroll
        for (int ks = 0; ks < 16; ks += 8) {
            uint32_t af[4][4], bf[4][2];
            #pragma unroll
            for (int mt = 0; mt < 4; mt++) {
                int r = wm * 64 + mt * 16;
                af[mt][0] = As[r + g][ks + tig];
                af[mt][1] = As[r + g + 8][ks + tig];
                af[mt][2] = As[r + g][ks + tig + 4];
                af[mt][3] = As[r + g + 8][ks + tig + 4];
            }
            #pragma unroll
            for (int nt = 0; nt < 4; nt++) {
                int cc = wn * 32 + nt * 8 + g;
                bf[nt][0] = Bs[ks + tig][cc];
                bf[nt][1] = Bs[ks + tig + 4][cc];
            }
            #pragma unroll
            for (int mt = 0; mt < 4; mt++)
                #pragma unroll
                for (int nt = 0; nt < 4; nt++)
                    mma8(acc[mt][nt], af[mt], bf[nt]);
        }
        __syncthreads();
    }

    // epilogue: v relayout or sigmoid gate
    #pragma unroll
    for (int mt = 0; mt < 4; mt++) {
        #pragma unroll
        for (int half = 0; half < 2; half++) {
            int i = i0 + wm * 64 + mt * 16 + g + half * 8;
            int s = i / N_DIM, n = i % N_DIM;
            #pragma unroll
            for (int nt = 0; nt < 4; nt++) {
                int colp = wn * 32 + nt * 8 + 2 * tig;
                float v0 = acc[mt][nt][half * 2];
                float v1 = acc[mt][nt][half * 2 + 1];
                if (cy < 2) {
                    int colg = cy * 128 + colp;
                    int hh = colg >> 5, cc = colg & 31;
                    float2 st = {v0, v1};
                    *(float2*)(g_v + (size_t)(hh * N_DIM + n) * M_DIM + s * C_DIM + cc) = st;
                } else {
                    float2 st = {1.0f / (1.0f + __expf(-v0)),
                                 1.0f / (1.0f + __expf(-v1))};
                    *(float2*)(g_gate + (size_t)i * HC + (cy - 2) * 128 + colp) = st;
                }
            }
        }
    }
}

// ---------------- K2: LN(z) over 128 + @W2 -> b[h][j][i] ----------------
__global__ void ln_z_bias_kernel(const float* __restrict__ z,
                                 const float* __restrict__ gz,
                                 const float* __restrict__ bz,
                                 const float* __restrict__ W2) {
    __shared__ float szn[CZ];
    __shared__ float sW2[CZ * H_DIM];
    __shared__ float red[8];
    int t = threadIdx.x;                          // 128
    int j = blockIdx.x;
    int i = blockIdx.y;
    const float* row = z + ((size_t)i * N_DIM + j) * CZ;
    float x = row[t];
    #pragma unroll
    for (int l = 0; l < 8; l++) sW2[t + l * 128] = W2[t + l * 128];

    float s = x, ss = x * x;
    #pragma unroll
    for (int o = 16; o > 0; o >>= 1) {
        s  += __shfl_xor_sync(0xffffffffu, s,  o);
        ss += __shfl_xor_sync(0xffffffffu, ss, o);
    }
    int warp = t >> 5, lane = t & 31;
    if (lane == 0) { red[warp] = s; red[4 + warp] = ss; }
    __syncthreads();
    float stot  = red[0] + red[1] + red[2] + red[3];
    float sstot = red[4] + red[5] + red[6] + red[7];
    float mu  = stot * (1.0f / 128.0f);
    float var = sstot * (1.0f / 128.0f) - mu * mu;
    float inv = rsqrtf(var + 1e-5f);
    szn[t] = (x - mu) * inv * gz[t] + bz[t];
    __syncthreads();
    if (t < H_DIM) {
        float acc = 0.0f;
        #pragma unroll 8
        for (int k = 0; k < CZ; k++) acc += szn[k] * sW2[k * H_DIM + t];
        g_b[((size_t)t * N_DIM + j) * N_DIM + i] = acc;
    }
}

// ---------------- K3: softmax over i (contiguous), write w[h][i][j] ----------------
__global__ void softmax_kernel() {
    __shared__ float redm[4];
    __shared__ float reds[4];
    int j = blockIdx.x;
    int h = blockIdx.y;
    int t = threadIdx.x;                          // 128
    const float* col = g_b + ((size_t)h * N_DIM + j) * N_DIM;
    float v0 = col[t], v1 = col[t + 128], v2 = col[t + 256];
    float mx = fmaxf(v0, fmaxf(v1, v2));
    #pragma unroll
    for (int o = 16; o > 0; o >>= 1) mx = fmaxf(mx, __shfl_xor_sync(0xffffffffu, mx, o));
    int warp = t >> 5, lane = t & 31;
    if (lane == 0) redm[warp] = mx;
    __syncthreads();
    mx = fmaxf(fmaxf(redm[0], redm[1]), fmaxf(redm[2], redm[3]));
    float e0 = __expf(v0 - mx), e1 = __expf(v1 - mx), e2 = __expf(v2 - mx);
    float sm = e0 + e1 + e2;
    #pragma unroll
    for (int o = 16; o > 0; o >>= 1) sm += __shfl_xor_sync(0xffffffffu, sm, o);
    if (lane == 0) reds[warp] = sm;
    __syncthreads();
    float inv = 1.0f / (reds[0] + reds[1] + reds[2] + reds[3]);
    float* wbase = g_w + (size_t)h * N_DIM * N_DIM + j;
    wbase[(size_t)(t)       * N_DIM] = e0 * inv;
    wbase[(size_t)(t + 128) * N_DIM] = e1 * inv;
    wbase[(size_t)(t + 256) * N_DIM] = e2 * inv;
}

// ---------------- K4: tf32-MMA per-head GEMM  wv_h[i,m] = w_h[i,j] @ v_h[j,m] ------
// Block 128(i) x 128(m), K=384 chunked by 16. 8 warps: 2 (M) x 4 (N), warp tile 64x32.
__global__ __launch_bounds__(256) void gemm_wv_mma() {
    __shared__ uint32_t As[128][20];
    __shared__ uint32_t Bs[16][136];
    int t = threadIdx.x;
    int lane = t & 31, w = t >> 5;
    int wm = w & 1, wn = w >> 1;
    int g = lane >> 2, tig = lane & 3;
    int m0 = blockIdx.x * 128;
    int i0 = blockIdx.y * 128;
    int h  = blockIdx.z;
    const float* A  = g_w + (size_t)h * N_DIM * N_DIM;   // [i][j]
    const float* Bv = g_v + (size_t)h * N_DIM * M_DIM;   // [j][m]

    float acc[4][4][4];
    #pragma unroll
    for (int a = 0; a < 4; a++)
        #pragma unroll
        for (int b = 0; b < 4; b++)
            #pragma unroll
            for (int q = 0; q < 4; q++) acc[a][b][q] = 0.0f;

    for (int k0 = 0; k0 < N_DIM; k0 += 16) {
        {
            int row = t >> 1, kh = (t & 1) * 8;
            const float* src = A + (size_t)(i0 + row) * N_DIM + k0 + kh;
            float4 v0 = *(const float4*)src;
            float4 v1 = *(const float4*)(src + 4);
            uint32_t* d = &As[row][kh];
            d[0] = f2tf(v0.x); d[1] = f2tf(v0.y); d[2] = f2tf(v0.z); d[3] = f2tf(v0.w);
            d[4] = f2tf(v1.x); d[5] = f2tf(v1.y); d[6] = f2tf(v1.z); d[7] = f2tf(v1.w);
        }
        {
            int kk = t >> 4, mc = (t & 15) * 8;
            const float* src = Bv + (size_t)(k0 + kk) * M_DIM + m0 + mc;
            float4 v0 = *(const float4*)src;
            float4 v1 = *(const float4*)(src + 4);
            uint32_t* d = &Bs[kk][mc];
            d[0] = f2tf(v0.x); d[1] = f2tf(v0.y); d[2] = f2tf(v0.z); d[3] = f2tf(v0.w);
            d[4] = f2tf(v1.x); d[5] = f2tf(v1.y); d[6] = f2tf(v1.z); d[7] = f2tf(v1.w);
        }
        __syncthreads();
        #pragma unroll
        for (int ks = 0; ks < 16; ks += 8) {
            uint32_t af[4][4], bf[4][2];
            #pragma unroll
            for (int mt = 0; mt < 4; mt++) {
                int r = wm * 64 + mt * 16;
                af[mt][0] = As[r + g][ks + tig];
                af[mt][1] = As[r + g + 8][ks + tig];
                af[mt][2] = As[r + g][ks + tig + 4];
                af[mt][3] = As[r + g + 8][ks + tig + 4];
            }
            #pragma unroll
            for (int nt = 0; nt < 4; nt++) {
                int cc = wn * 32 + nt * 8 + g;
                bf[nt][0] = Bs[ks + tig][cc];
                bf[nt][1] = Bs[ks + tig + 4][cc];
            }
            #pragma unroll
            for (int mt = 0; mt < 4; mt++)
                #pragma unroll
                for (int nt = 0; nt < 4; nt++)
                    mma8(acc[mt][nt], af[mt], bf[nt]);
        }
        __syncthreads();
    }

    float* dsth = g_wv + (size_t)h * N_DIM * M_DIM;
    #pragma unroll
    for (int mt = 0; mt < 4; mt++) {
        int r = i0 + wm * 64 + mt * 16 + g;
        #pragma unroll
        for (int nt = 0; nt < 4; nt++) {
            int col = m0 + wn * 32 + nt * 8 + 2 * tig;
            float2 v0 = {acc[mt][nt][0], acc[mt][nt][1]};
            float2 v1 = {acc[mt][nt][2], acc[mt][nt][3]};
            *(float2*)(dsth + (size_t)r * M_DIM + col) = v0;
            *(float2*)(dsth + (size_t)(r + 8) * M_DIM + col) = v1;
        }
    }
}

// ---------------- K5: tf32-MMA  out[r,64] = (gate[r,:]*wv_gather[r,:]) @ W4 ----------
// Block 128 rows x 64 cols, K=256 chunked by 32 (one head per chunk).
// 8 warps: 4 (M) x 2 (N), warp tile 32x32.
__global__ __launch_bounds__(256) void final_mma(const float* __restrict__ W4,
                                                 float* __restrict__ out) {
    __shared__ uint32_t Os[128][36];   // [row][k] pitch 36
    __shared__ uint32_t Ws[32][72];    // [k][n]  pitch 72
    int t = threadIdx.x;
    int lane = t & 31, w = t >> 5;
    int wm = w >> 1, wn = w & 1;       // 4 x 2
    int g = lane >> 2, tig = lane & 3;
    int r0 = blockIdx.x * 128;

    float acc[2][4][4];
    #pragma unroll
    for (int a = 0; a < 2; a++)
        #pragma unroll
        for (int b = 0; b < 4; b++)
            #pragma unroll
            for (int q = 0; q < 4; q++) acc[a][b][q] = 0.0f;

    for (int k0 = 0; k0 < HC; k0 += 32) {
        int h = k0 >> 5;
        // stage O = gate * wv (gathered), 128 x 32
        {
            int row = t >> 1, kh = (t & 1) * 16;
            int r = r0 + row;
            int s = r / N_DIM, n = r % N_DIM;
            const float* wvs = g_wv + (size_t)(h * N_DIM + n) * M_DIM + s * C_DIM + kh;
            const float* gts = g_gate + (size_t)r * HC + k0 + kh;
            uint32_t* d = &Os[row][kh];
            #pragma unroll
            for (int u = 0; u < 4; u++) {
                float4 a4 = *(const float4*)(wvs + u * 4);
                float4 g4 = *(const float4*)(gts + u * 4);
                d[u * 4 + 0] = f2tf(a4.x * g4.x);
                d[u * 4 + 1] = f2tf(a4.y * g4.y);
                d[u * 4 + 2] = f2tf(a4.z * g4.z);
                d[u * 4 + 3] = f2tf(a4.w * g4.w);
            }
        }
        // stage W4 chunk: 32 x 64
        {
            int kk = t >> 3, nc = (t & 7) * 8;
            const float* src = W4 + (size_t)(k0 + kk) * CM + nc;
            float4 v0 = *(const float4*)src;
            float4 v1 = *(const float4*)(src + 4);
            uint32_t* d = &Ws[kk][nc];
            d[0] = f2tf(v0.x); d[1] = f2tf(v0.y); d[2] = f2tf(v0.z); d[3] = f2tf(v0.w);
            d[4] = f2tf(v1.x); d[5] = f2tf(v1.y); d[6] = f2tf(v1.z); d[7] = f2tf(v1.w);
        }
        __syncthreads();
        #pragma unroll
        for (int ks = 0; ks < 32; ks += 8) {
            uint32_t af[2][4], bf[4][2];
            #pragma unroll
            for (int mt = 0; mt < 2; mt++) {
                int r = wm * 32 + mt * 16;
                af[mt][0] = Os[r + g][ks + tig];
                af[mt][1] = Os[r + g + 8][ks + tig];
                af[mt][2] = Os[r + g][ks + tig + 4];
                af[mt][3] = Os[r + g + 8][ks + tig + 4];
            }
            #pragma unroll
            for (int nt = 0; nt < 4; nt++) {
                int cc = wn * 32 + nt * 8 + g;
                bf[nt][0] = Ws[ks + tig][cc];
                bf[nt][1] = Ws[ks + tig + 4][cc];
            }
            #pragma unroll
            for (int mt = 0; mt < 2; mt++)
                #pragma unroll
                for (int nt = 0; nt < 4; nt++)
                    mma8(acc[mt][nt], af[mt], bf[nt]);
        }
        __syncthreads();
    }

    #pragma unroll
    for (int mt = 0; mt < 2; mt++) {
        int r = r0 + wm * 32 + mt * 16 + g;
        #pragma unroll
        for (int nt = 0; nt < 4; nt++) {
            int col = wn * 32 + nt * 8 + 2 * tig;
            float2 v0 = {acc[mt][nt][0], acc[mt][nt][1]};
            float2 v1 = {acc[mt][nt][2], acc[mt][nt][3]};
            *(float2*)(out + (size_t)r * CM + col) = v0;
            *(float2*)(out + (size_t)(r + 8) * CM + col) = v1;
        }
    }
}

// ---------------- launch ----------------
extern "C" void kernel_launch(void* const* d_in, const int* in_sizes, int n_in,
                              void* d_out, int out_size) {
    const float* m_si    = (const float*)d_in[0];
    const float* z_ij    = (const float*)d_in[1];
    const float* gamma_m = (const float*)d_in[2];
    const float* beta_m  = (const float*)d_in[3];
    const float* W1      = (const float*)d_in[4];
    const float* gamma_z = (const float*)d_in[5];
    const float* beta_z  = (const float*)d_in[6];
    const float* W2      = (const float*)d_in[7];
    const float* W3      = (const float*)d_in[8];
    const float* W4      = (const float*)d_in[9];
    float* out = (float*)d_out;

    ln_m_kernel<<<SN / 8, 256>>>(m_si, gamma_m, beta_m);
    gemm_mw_mma<<<dim3(SN / 128, 4), 256>>>(W1, W3);
    ln_z_bias_kernel<<<dim3(N_DIM, N_DIM), 128>>>(z_ij, gamma_z, beta_z, W2);
    softmax_kernel<<<dim3(N_DIM, H_DIM), 128>>>();
    gemm_wv_mma<<<dim3(M_DIM / 128, N_DIM / 128, H_DIM), 256>>>();
    final_mma<<<SN / 128, 256>>>(W4, out);
}

// round 5
// speedup vs baseline: 2.6730x; 1.0429x over previous
#include <cuda_runtime.h>
#include <math.h>
#include <stdint.h>

// Problem constants
#define S_DIM 512
#define N_DIM 384
#define CM 64
#define CZ 128
#define H_DIM 8
#define C_DIM 32
#define HC 256                  // H*C
#define SN (S_DIM * N_DIM)      // 196608 rows of m
#define M_DIM (S_DIM * C_DIM)   // 16384 = columns of the einsum GEMM

// ---------------- scratch (device globals; no allocation allowed) ----------------
__device__ float g_mn[SN * CM];                    // normalized m (tf32-rounded)
__device__ float g_v[H_DIM * N_DIM * M_DIM];       // v [h][j][s*32+c] (tf32-rounded)
__device__ float g_gate[SN * HC];                  // sigmoid gate [row][k]
__device__ float g_b[H_DIM * N_DIM * N_DIM];       // bias [h][j][i]
__device__ float g_w[H_DIM * N_DIM * N_DIM];       // softmax w [h][i][j] (tf32-rounded)
__device__ float g_wv[H_DIM * N_DIM * M_DIM];      // wv [h][i][s*32+c]
__device__ float g_w1t[CM * HC];                   // W1 tf32-rounded
__device__ float g_w3t[CM * HC];                   // W3 tf32-rounded
__device__ float g_w4t[HC * CM];                   // W4 tf32-rounded

// ---------------- helpers ----------------
__device__ __forceinline__ uint32_t f2tf(float x) {
    uint32_t y;
    asm("cvt.rna.tf32.f32 %0, %1;" : "=r"(y) : "f"(x));
    return y;
}
__device__ __forceinline__ float f2tff(float x) { return __uint_as_float(f2tf(x)); }

__device__ __forceinline__ void mma8(float c[4], const uint32_t a[4], const uint32_t b[2]) {
    asm volatile(
        "mma.sync.aligned.m16n8k8.row.col.f32.tf32.tf32.f32 "
        "{%0,%1,%2,%3}, {%4,%5,%6,%7}, {%8,%9}, {%0,%1,%2,%3};\n"
        : "+f"(c[0]), "+f"(c[1]), "+f"(c[2]), "+f"(c[3])
        : "r"(a[0]), "r"(a[1]), "r"(a[2]), "r"(a[3]), "r"(b[0]), "r"(b[1]));
}

// ---------------- K0: round weights to tf32 ----------------
__global__ void round_weights(const float* __restrict__ W1,
                              const float* __restrict__ W3,
                              const float* __restrict__ W4) {
    int i = blockIdx.x * blockDim.x + threadIdx.x;
    if (i < CM * HC) g_w1t[i] = f2tff(W1[i]);
    if (i < CM * HC) g_w3t[i] = f2tff(W3[i]);
    if (i < HC * CM) g_w4t[i] = f2tff(W4[i]);
}

// ---------------- K1a: LayerNorm over c_m=64, one warp per row ----------------
__global__ void ln_m_kernel(const float* __restrict__ x,
                            const float* __restrict__ gamma,
                            const float* __restrict__ beta) {
    int warp = (blockIdx.x * blockDim.x + threadIdx.x) >> 5;
    int lane = threadIdx.x & 31;
    if (warp >= SN) return;
    const float* row = x + (size_t)warp * CM;
    float a = row[lane];
    float b = row[lane + 32];
    float s = a + b;
    float ss = a * a + b * b;
    #pragma unroll
    for (int o = 16; o > 0; o >>= 1) {
        s  += __shfl_xor_sync(0xffffffffu, s,  o);
        ss += __shfl_xor_sync(0xffffffffu, ss, o);
    }
    float mu  = s * (1.0f / 64.0f);
    float var = ss * (1.0f / 64.0f) - mu * mu;
    float inv = rsqrtf(var + 1e-5f);
    float* out = g_mn + (size_t)warp * CM;
    out[lane]      = f2tff((a - mu) * inv * gamma[lane]      + beta[lane]);
    out[lane + 32] = f2tff((b - mu) * inv * gamma[lane + 32] + beta[lane + 32]);
}

// ============ shared mma-tile machinery (128x128 CTA tile, K-chunk 16) ============
// As: k-pair-interleaved [row][24] (pitch 24 words, conflict-free LDS.64)
//   element (row, k) lives at As[row][(k&3)*2 + ((k>>2)&1) + (k&8)]
// Bs: [k][col] pitch 136.
struct TileSmem {
    uint32_t As[128][24];
    uint32_t Bs[16][136];
};

__device__ __forceinline__ void mma_tile16(float acc[4][4][4], const TileSmem* sm,
                                           int wm, int wn, int g, int tig) {
    #pragma unroll
    for (int ks = 0; ks < 16; ks += 8) {
        uint32_t af[4][4], bf[4][2];
        #pragma unroll
        for (int mt = 0; mt < 4; mt++) {
            int r = wm * 64 + mt * 16;
            uint2 ld0 = *(const uint2*)&sm->As[r + g][tig * 2 + ks];
            uint2 ld1 = *(const uint2*)&sm->As[r + g + 8][tig * 2 + ks];
            af[mt][0] = ld0.x; af[mt][2] = ld0.y;
            af[mt][1] = ld1.x; af[mt][3] = ld1.y;
        }
        #pragma unroll
        for (int nt = 0; nt < 4; nt++) {
            int cc = wn * 32 + nt * 8 + g;
            bf[nt][0] = sm->Bs[ks + tig][cc];
            bf[nt][1] = sm->Bs[ks + tig + 4][cc];
        }
        #pragma unroll
        for (int mt = 0; mt < 4; mt++)
            #pragma unroll
            for (int nt = 0; nt < 4; nt++)
                mma8(acc[mt][nt], af[mt], bf[nt]);
    }
}

// store prefetched regs into smem (thread roles: A row=t>>1, kh=(t&1)*8; B kk=t>>4, mc=(t&15)*8)
__device__ __forceinline__ void stage_regs(TileSmem* sm, int t,
                                           const float4& pa0, const float4& pa1,
                                           const float4& pb0, const float4& pb1) {
    int arow = t >> 1, akh = (t & 1) * 8;
    const float a0[4] = {pa0.x, pa0.y, pa0.z, pa0.w};
    const float a1[4] = {pa1.x, pa1.y, pa1.z, pa1.w};
    #pragma unroll
    for (int j = 0; j < 4; j++) {
        uint2 st = {__float_as_uint(a0[j]), __float_as_uint(a1[j])};
        *(uint2*)&sm->As[arow][akh + 2 * j] = st;
    }
    int bkk = t >> 4, bmc = (t & 15) * 8;
    *(float4*)&sm->Bs[bkk][bmc]     = pb0;
    *(float4*)&sm->Bs[bkk][bmc + 4] = pb1;
}

// ---------------- K1b: tf32-MMA GEMM [SN x 64] @ [64 x 512] -> v + gate ----------
__global__ __launch_bounds__(256, 2) void gemm_mw_mma() {
    __shared__ TileSmem sm;
    int t = threadIdx.x;
    int lane = t & 31, w = t >> 5;
    int wm = w & 1, wn = w >> 1;
    int g = lane >> 2, tig = lane & 3;
    int i0 = blockIdx.x * 128;
    int cy = blockIdx.y;                          // 0,1 -> W1 ; 2,3 -> W3
    const float* B = (cy < 2) ? g_w1t : g_w3t;
    int col0 = (cy & 1) * 128;

    float acc[4][4][4];
    #pragma unroll
    for (int a = 0; a < 4; a++)
        #pragma unroll
        for (int b = 0; b < 4; b++)
            #pragma unroll
            for (int q = 0; q < 4; q++) acc[a][b][q] = 0.0f;

    int arow = t >> 1, akh = (t & 1) * 8;
    int bkk = t >> 4, bmc = (t & 15) * 8;
    const float* Ap = g_mn + (size_t)(i0 + arow) * CM + akh;
    const float* Bp = B + (size_t)bkk * HC + col0 + bmc;

    float4 pa0 = *(const float4*)Ap;
    float4 pa1 = *(const float4*)(Ap + 4);
    float4 pb0 = *(const float4*)Bp;
    float4 pb1 = *(const float4*)(Bp + 4);

    #pragma unroll 1
    for (int c = 0; c < 4; c++) {
        stage_regs(&sm, t, pa0, pa1, pb0, pb1);
        __syncthreads();
        if (c + 1 < 4) {
            Ap += 16;
            Bp += 16 * HC;
            pa0 = *(const float4*)Ap;
            pa1 = *(const float4*)(Ap + 4);
            pb0 = *(const float4*)Bp;
            pb1 = *(const float4*)(Bp + 4);
        }
        mma_tile16(acc, &sm, wm, wn, g, tig);
        __syncthreads();
    }

    // epilogue: v (tf32-rounded, [h][j][m] layout) or sigmoid gate
    #pragma unroll
    for (int mt = 0; mt < 4; mt++) {
        #pragma unroll
        for (int half = 0; half < 2; half++) {
            int i = i0 + wm * 64 + mt * 16 + g + half * 8;
            int s = i / N_DIM, n = i % N_DIM;
            #pragma unroll
            for (int nt = 0; nt < 4; nt++) {
                int colp = wn * 32 + nt * 8 + 2 * tig;
                float v0 = acc[mt][nt][half * 2];
                float v1 = acc[mt][nt][half * 2 + 1];
                if (cy < 2) {
                    int colg = cy * 128 + colp;
                    int hh = colg >> 5, cc = colg & 31;
                    float2 st = {f2tff(v0), f2tff(v1)};
                    *(float2*)(g_v + (size_t)(hh * N_DIM + n) * M_DIM + s * C_DIM + cc) = st;
                } else {
                    float2 st = {1.0f / (1.0f + __expf(-v0)),
                                 1.0f / (1.0f + __expf(-v1))};
                    *(float2*)(g_gate + (size_t)i * HC + (cy - 2) * 128 + colp) = st;
                }
            }
        }
    }
}

// ---------------- K2: LN(z) over 128 + @W2 -> b[h][j][i] ----------------
__global__ void ln_z_bias_kernel(const float* __restrict__ z,
                                 const float* __restrict__ gz,
                                 const float* __restrict__ bz,
                                 const float* __restrict__ W2) {
    __shared__ float szn[CZ];
    __shared__ float sW2[CZ * H_DIM];
    __shared__ float red[8];
    int t = threadIdx.x;
    int j = blockIdx.x;
    int i = blockIdx.y;
    const float* row = z + ((size_t)i * N_DIM + j) * CZ;
    float x = row[t];
    #pragma unroll
    for (int l = 0; l < 8; l++) sW2[t + l * 128] = W2[t + l * 128];

    float s = x, ss = x * x;
    #pragma unroll
    for (int o = 16; o > 0; o >>= 1) {
        s  += __shfl_xor_sync(0xffffffffu, s,  o);
        ss += __shfl_xor_sync(0xffffffffu, ss, o);
    }
    int warp = t >> 5, lane = t & 31;
    if (lane == 0) { red[warp] = s; red[4 + warp] = ss; }
    __syncthreads();
    float stot  = red[0] + red[1] + red[2] + red[3];
    float sstot = red[4] + red[5] + red[6] + red[7];
    float mu  = stot * (1.0f / 128.0f);
    float var = sstot * (1.0f / 128.0f) - mu * mu;
    float inv = rsqrtf(var + 1e-5f);
    szn[t] = (x - mu) * inv * gz[t] + bz[t];
    __syncthreads();
    if (t < H_DIM) {
        float acc = 0.0f;
        #pragma unroll 8
        for (int k = 0; k < CZ; k++) acc += szn[k] * sW2[k * H_DIM + t];
        g_b[((size_t)t * N_DIM + j) * N_DIM + i] = acc;
    }
}

// ---------------- K3: softmax over i (contiguous), write w[h][i][j] tf32 -----------
__global__ void softmax_kernel() {
    __shared__ float redm[4];
    __shared__ float reds[4];
    int j = blockIdx.x;
    int h = blockIdx.y;
    int t = threadIdx.x;
    const float* col = g_b + ((size_t)h * N_DIM + j) * N_DIM;
    float v0 = col[t], v1 = col[t + 128], v2 = col[t + 256];
    float mx = fmaxf(v0, fmaxf(v1, v2));
    #pragma unroll
    for (int o = 16; o > 0; o >>= 1) mx = fmaxf(mx, __shfl_xor_sync(0xffffffffu, mx, o));
    int warp = t >> 5, lane = t & 31;
    if (lane == 0) redm[warp] = mx;
    __syncthreads();
    mx = fmaxf(fmaxf(redm[0], redm[1]), fmaxf(redm[2], redm[3]));
    float e0 = __expf(v0 - mx), e1 = __expf(v1 - mx), e2 = __expf(v2 - mx);
    float sm = e0 + e1 + e2;
    #pragma unroll
    for (int o = 16; o > 0; o >>= 1) sm += __shfl_xor_sync(0xffffffffu, sm, o);
    if (lane == 0) reds[warp] = sm;
    __syncthreads();
    float inv = 1.0f / (reds[0] + reds[1] + reds[2] + reds[3]);
    float* wbase = g_w + (size_t)h * N_DIM * N_DIM + j;
    wbase[(size_t)(t)       * N_DIM] = f2tff(e0 * inv);
    wbase[(size_t)(t + 128) * N_DIM] = f2tff(e1 * inv);
    wbase[(size_t)(t + 256) * N_DIM] = f2tff(e2 * inv);
}

// ---------------- K4: tf32-MMA per-head GEMM  wv_h[i,m] = w_h[i,j] @ v_h[j,m] ------
__global__ __launch_bounds__(256, 2) void gemm_wv_mma() {
    __shared__ TileSmem sm;
    int t = threadIdx.x;
    int lane = t & 31, w = t >> 5;
    int wm = w & 1, wn = w >> 1;
    int g = lane >> 2, tig = lane & 3;
    int i0 = blockIdx.x * 128;           // 3 i-tiles (fastest -> v-tile L2 reuse)
    int m0 = blockIdx.y * 128;           // 128 m-tiles
    int h  = blockIdx.z;
    const float* A  = g_w + (size_t)h * N_DIM * N_DIM;   // [i][j]
    const float* Bv = g_v + (size_t)h * N_DIM * M_DIM;   // [j][m]

    float acc[4][4][4];
    #pragma unroll
    for (int a = 0; a < 4; a++)
        #pragma unroll
        for (int b = 0; b < 4; b++)
            #pragma unroll
            for (int q = 0; q < 4; q++) acc[a][b][q] = 0.0f;

    int arow = t >> 1, akh = (t & 1) * 8;
    int bkk = t >> 4, bmc = (t & 15) * 8;
    const float* Ap = A + (size_t)(i0 + arow) * N_DIM + akh;
    const float* Bp = Bv + (size_t)bkk * M_DIM + m0 + bmc;

    float4 pa0 = *(const float4*)Ap;
    float4 pa1 = *(const float4*)(Ap + 4);
    float4 pb0 = *(const float4*)Bp;
    float4 pb1 = *(const float4*)(Bp + 4);

    #pragma unroll 1
    for (int c = 0; c < 24; c++) {
        stage_regs(&sm, t, pa0, pa1, pb0, pb1);
        __syncthreads();
        if (c + 1 < 24) {
            Ap += 16;
            Bp += (size_t)16 * M_DIM;
            pa0 = *(const float4*)Ap;
            pa1 = *(const float4*)(Ap + 4);
            pb0 = *(const float4*)Bp;
            pb1 = *(const float4*)(Bp + 4);
        }
        mma_tile16(acc, &sm, wm, wn, g, tig);
        __syncthreads();
    }

    float* dsth = g_wv + (size_t)h * N_DIM * M_DIM;
    #pragma unroll
    for (int mt = 0; mt < 4; mt++) {
        int r = i0 + wm * 64 + mt * 16 + g;
        #pragma unroll
        for (int nt = 0; nt < 4; nt++) {
            int col = m0 + wn * 32 + nt * 8 + 2 * tig;
            float2 v0 = {acc[mt][nt][0], acc[mt][nt][1]};
            float2 v1 = {acc[mt][nt][2], acc[mt][nt][3]};
            *(float2*)(dsth + (size_t)r * M_DIM + col) = v0;
            *(float2*)(dsth + (size_t)(r + 8) * M_DIM + col) = v1;
        }
    }
}

// ---------------- K5: tf32-MMA  out[r,64] = (gate[r,:]*wv_gather[r,:]) @ W4 ----------
__global__ __launch_bounds__(256) void final_mma(float* __restrict__ out) {
    __shared__ uint32_t Os[128][36];
    __shared__ uint32_t Ws[32][72];
    int t = threadIdx.x;
    int lane = t & 31, w = t >> 5;
    int wm = w >> 1, wn = w & 1;
    int g = lane >> 2, tig = lane & 3;
    int r0 = blockIdx.x * 128;

    float acc[2][4][4];
    #pragma unroll
    for (int a = 0; a < 2; a++)
        #pragma unroll
        for (int b = 0; b < 4; b++)
            #pragma unroll
            for (int q = 0; q < 4; q++) acc[a][b][q] = 0.0f;

    for (int k0 = 0; k0 < HC; k0 += 32) {
        int h = k0 >> 5;
        {
            int row = t >> 1, kh = (t & 1) * 16;
            int r = r0 + row;
            int s = r / N_DIM, n = r % N_DIM;
            const float* wvs = g_wv + (size_t)(h * N_DIM + n) * M_DIM + s * C_DIM + kh;
            const float* gts = g_gate + (size_t)r * HC + k0 + kh;
            uint32_t* d = &Os[row][kh];
            #pragma unroll
            for (int u = 0; u < 4; u++) {
                float4 a4 = *(const float4*)(wvs + u * 4);
                float4 g4 = *(const float4*)(gts + u * 4);
                d[u * 4 + 0] = f2tf(a4.x * g4.x);
                d[u * 4 + 1] = f2tf(a4.y * g4.y);
                d[u * 4 + 2] = f2tf(a4.z * g4.z);
                d[u * 4 + 3] = f2tf(a4.w * g4.w);
            }
        }
        {
            int kk = t >> 3, nc = (t & 7) * 8;
            const float* src = g_w4t + (size_t)(k0 + kk) * CM + nc;
            *(float4*)&Ws[kk][nc]     = *(const float4*)src;
            *(float4*)&Ws[kk][nc + 4] = *(const float4*)(src + 4);
        }
        __syncthreads();
        #pragma unroll
        for (int ks = 0; ks < 32; ks += 8) {
            uint32_t af[2][4], bf[4][2];
            #pragma unroll
            for (int mt = 0; mt < 2; mt++) {
                int r = wm * 32 + mt * 16;
                af[mt][0] = Os[r + g][ks + tig];
                af[mt][1] = Os[r + g + 8][ks + tig];
                af[mt][2] = Os[r + g][ks + tig + 4];
                af[mt][3] = Os[r + g + 8][ks + tig + 4];
            }
            #pragma unroll
            for (int nt = 0; nt < 4; nt++) {
                int cc = wn * 32 + nt * 8 + g;
                bf[nt][0] = Ws[ks + tig][cc];
                bf[nt][1] = Ws[ks + tig + 4][cc];
            }
            #pragma unroll
            for (int mt = 0; mt < 2; mt++)
                #pragma unroll
                for (int nt = 0; nt < 4; nt++)
                    mma8(acc[mt][nt], af[mt], bf[nt]);
        }
        __syncthreads();
    }

    #pragma unroll
    for (int mt = 0; mt < 2; mt++) {
        int r = r0 + wm * 32 + mt * 16 + g;
        #pragma unroll
        for (int nt = 0; nt < 4; nt++) {
            int col = wn * 32 + nt * 8 + 2 * tig;
            float2 v0 = {acc[mt][nt][0], acc[mt][nt][1]};
            float2 v1 = {acc[mt][nt][2], acc[mt][nt][3]};
            *(float2*)(out + (size_t)r * CM + col) = v0;
            *(float2*)(out + (size_t)(r + 8) * CM + col) = v1;
        }
    }
}

// ---------------- launch ----------------
extern "C" void kernel_launch(void* const* d_in, const int* in_sizes, int n_in,
                              void* d_out, int out_size) {
    const float* m_si    = (const float*)d_in[0];
    const float* z_ij    = (const float*)d_in[1];
    const float* gamma_m = (const float*)d_in[2];
    const float* beta_m  = (const float*)d_in[3];
    const float* W1      = (const float*)d_in[4];
    const float* gamma_z = (const float*)d_in[5];
    const float* beta_z  = (const float*)d_in[6];
    const float* W2      = (const float*)d_in[7];
    const float* W3      = (const float*)d_in[8];
    const float* W4      = (const float*)d_in[9];
    float* out = (float*)d_out;

    round_weights<<<(CM * HC + 255) / 256, 256>>>(W1, W3, W4);
    ln_m_kernel<<<SN / 8, 256>>>(m_si, gamma_m, beta_m);
    gemm_mw_mma<<<dim3(SN / 128, 4), 256>>>();
    ln_z_bias_kernel<<<dim3(N_DIM, N_DIM), 128>>>(z_ij, gamma_z, beta_z, W2);
    softmax_kernel<<<dim3(N_DIM, H_DIM), 128>>>();
    gemm_wv_mma<<<dim3(N_DIM / 128, M_DIM / 128, H_DIM), 256>>>();
    final_mma<<<SN / 128, 256>>>(out);
}